// round 16
// baseline (speedup 1.0000x reference)
#include <cuda_runtime.h>
#include <cuda_bf16.h>
#include <cstdint>
#include <cstddef>

#define NN 100000
#define EE 1600000
#define HF 128
#define KIN 512
#define NBLK 98     // ceil(NN/1024)
#define GRID_M 782  // ceil(NN/128)
#define BK 64
#define ASTR 72     // padded smem row stride (bf16 elems)

typedef __nv_bfloat16 bf16;

// ---------------- scratch (static device globals; no allocations) ----------------
__device__ int   g_is64;
__device__ float g_invnorm[NN];
__device__ int   g_cnt[NN];
__device__ float g_dinv[NN];
__device__ int   g_erow[EE];
__device__ int   g_ecol0[EE];
__device__ int   g_off[NN + 1];
__device__ int   g_cursor[NN];
__device__ int   g_bsum[128];
__device__ int   g_boff[128];
__device__ int2  g_epk[EE];          // packed (col, w-bits)

__device__ float g_h  [(size_t)NN * HF];
__device__ float g_za [(size_t)NN * HF];
__device__ float g_zb [(size_t)NN * HF];
__device__ float g_zc [(size_t)NN * HF];
__device__ float g_cat[(size_t)NN * 4 * HF];
__device__ float g_racc[(size_t)NN * HF];

// transposed + hi/lo split weights: Wt[n][k] = W[k][n]
__device__ bf16 g_wu_hi[HF * KIN];
__device__ bf16 g_wu_lo[HF * KIN];
__device__ bf16 g_wi_hi[4 * HF * HF];
__device__ bf16 g_wi_lo[4 * HF * HF];
__device__ bf16 g_wr_hi[HF * KIN];
__device__ bf16 g_wr_lo[HF * KIN];

// ---------------- helpers ----------------
__device__ __forceinline__ uint32_t smem_to_u32(const void* p) {
    uint32_t a;
    asm("{ .reg .u64 t; cvta.to.shared.u64 t, %1; cvt.u32.u64 %0, t; }" : "=r"(a) : "l"(p));
    return a;
}
__device__ __forceinline__ uint32_t bpack(bf16 a, bf16 b) {
    __nv_bfloat162 t(a, b);
    return *reinterpret_cast<uint32_t*>(&t);
}
__device__ __forceinline__ void split2(float a, float b, uint32_t& hi, uint32_t& lo) {
    bf16 ha = __float2bfloat16(a), hb = __float2bfloat16(b);
    float ra = a - __bfloat162float(ha);
    float rb = b - __bfloat162float(hb);
    hi = bpack(ha, hb);
    lo = bpack(__float2bfloat16(ra), __float2bfloat16(rb));
}
__device__ __forceinline__ void ldsm4(uint32_t* r, uint32_t a) {
    asm volatile("ldmatrix.sync.aligned.m8n8.x4.shared.b16 {%0,%1,%2,%3}, [%4];"
        : "=r"(r[0]), "=r"(r[1]), "=r"(r[2]), "=r"(r[3]) : "r"(a));
}
__device__ __forceinline__ void ldsm2(uint32_t* r, uint32_t a) {
    asm volatile("ldmatrix.sync.aligned.m8n8.x2.shared.b16 {%0,%1}, [%2];"
        : "=r"(r[0]), "=r"(r[1]) : "r"(a));
}
__device__ __forceinline__ void mma16816(float* c, const uint32_t* a, const uint32_t* b) {
    asm volatile("mma.sync.aligned.m16n8k16.row.col.f32.bf16.bf16.f32 "
        "{%0,%1,%2,%3}, {%4,%5,%6,%7}, {%8,%9}, {%0,%1,%2,%3};"
        : "+f"(c[0]), "+f"(c[1]), "+f"(c[2]), "+f"(c[3])
        : "r"(a[0]), "r"(a[1]), "r"(a[2]), "r"(a[3]), "r"(b[0]), "r"(b[1]));
}

// cache-policy loads/stores
__device__ __forceinline__ float4 ld_cs4(const float* p) {   // streaming (evict-first)
    float4 v;
    asm volatile("ld.global.cs.v4.f32 {%0,%1,%2,%3}, [%4];"
        : "=f"(v.x), "=f"(v.y), "=f"(v.z), "=f"(v.w) : "l"(p));
    return v;
}
__device__ __forceinline__ unsigned long long mk_evict_last_policy() {
    unsigned long long pol;
    asm volatile("createpolicy.fractional.L2::evict_last.b64 %0, 1.0;" : "=l"(pol));
    return pol;
}
__device__ __forceinline__ float4 ld_el4(const float* p, unsigned long long pol) {
    float4 v;
    asm volatile("ld.global.nc.L2::cache_hint.v4.f32 {%0,%1,%2,%3}, [%4], %5;"
        : "=f"(v.x), "=f"(v.y), "=f"(v.z), "=f"(v.w) : "l"(p), "l"(pol));
    return v;
}
__device__ __forceinline__ float2 ld_cs2(const float* p) {
    float2 v;
    asm volatile("ld.global.cs.v2.f32 {%0,%1}, [%2];" : "=f"(v.x), "=f"(v.y) : "l"(p));
    return v;
}
__device__ __forceinline__ void st_cs2(float* p, float2 v) {
    asm volatile("st.global.cs.v2.f32 [%0], {%1,%2};" :: "l"(p), "f"(v.x), "f"(v.y));
}

// ---------------- preprocessing ----------------
__global__ void k_detect(const void* ei) {
    const unsigned int* p = (const unsigned int*)ei;
    int ok64 = 1;
    for (int i = threadIdx.x; i < 64; i += 32)
        if (p[2 * i + 1] != 0u) ok64 = 0;
    ok64 = __all_sync(0xffffffffu, ok64);
    if (threadIdx.x == 0) g_is64 = ok64;
}

__global__ void k_init_cnt() {
    int i = blockIdx.x * blockDim.x + threadIdx.x;
    if (i < NN) g_cnt[i] = 0;
}

__global__ void k_invnorm(const float* __restrict__ feats) {
    int w = (blockIdx.x * blockDim.x + threadIdx.x) >> 5;
    int lane = threadIdx.x & 31;
    if (w >= NN) return;
    const float* p = feats + (size_t)w * KIN;
    float ss = 0.f;
#pragma unroll
    for (int i = 0; i < 4; ++i) {
        float4 v = ld_cs4(p + (i * 32 + lane) * 4);
        ss += v.x * v.x + v.y * v.y + v.z * v.z + v.w * v.w;
    }
#pragma unroll
    for (int o = 16; o > 0; o >>= 1) ss += __shfl_xor_sync(0xffffffffu, ss, o);
    if (lane == 0) g_invnorm[w] = 1.0f / fmaxf(sqrtf(ss), 1e-12f);
}

__global__ void k_count(const void* ei) {
    int e = blockIdx.x * blockDim.x + threadIdx.x;
    if (e >= EE) return;
    int r, c;
    if (g_is64) {
        const long long* p = (const long long*)ei;
        r = (int)p[e]; c = (int)p[EE + e];
    } else {
        const int* p = (const int*)ei;
        r = p[e]; c = p[EE + e];
    }
    g_erow[e] = r;
    g_ecol0[e] = c;
    atomicAdd(&g_cnt[r], 1);
}

__global__ void k_scan1() {
    __shared__ int sm[1024];
    int t = threadIdx.x;
    int i = blockIdx.x * 1024 + t;
    int v = (i < NN) ? g_cnt[i] : 0;
    sm[t] = v;
    __syncthreads();
    for (int d = 1; d < 1024; d <<= 1) {
        int add = (t >= d) ? sm[t - d] : 0;
        __syncthreads();
        sm[t] += add;
        __syncthreads();
    }
    int incl = sm[t];
    if (i < NN) g_off[i] = incl - v;
    if (t == 1023) g_bsum[blockIdx.x] = incl;
}

__global__ void k_scan2() {
    __shared__ int sm[128];
    int t = threadIdx.x;
    int v = (t < NBLK) ? g_bsum[t] : 0;
    sm[t] = v;
    __syncthreads();
    for (int d = 1; d < 128; d <<= 1) {
        int add = (t >= d) ? sm[t - d] : 0;
        __syncthreads();
        sm[t] += add;
        __syncthreads();
    }
    g_boff[t] = sm[t] - v;
}

__global__ void k_scan3() {
    int t = threadIdx.x;
    int i = blockIdx.x * 1024 + t;
    if (i < NN) {
        int off = g_off[i] + g_boff[blockIdx.x];
        g_off[i] = off;
        g_cursor[i] = off;
        g_dinv[i] = rsqrtf((float)(g_cnt[i] + 1));
        if (i == 0) g_off[NN] = EE;
    }
}

__global__ void k_scatter() {
    int e = blockIdx.x * blockDim.x + threadIdx.x;
    if (e >= EE) return;
    int r = g_erow[e], c = g_ecol0[e];
    int pos = atomicAdd(&g_cursor[r], 1);
    g_epk[pos] = make_int2(c, __float_as_int(g_dinv[r] * g_dinv[c]));
}

// weight transpose + split: out[m][n][k] = W[m][k][n]
__global__ void k_wprep(const float* __restrict__ W, bf16* __restrict__ hi,
                        bf16* __restrict__ lo, int K, int total) {
    int o = blockIdx.x * blockDim.x + threadIdx.x;
    if (o >= total) return;
    int k = o % K;
    int rem = o / K;
    int n = rem % HF;
    int m = rem / HF;
    float x = W[(size_t)m * K * HF + (size_t)k * HF + n];
    bf16 h = __float2bfloat16(x);
    hi[o] = h;
    lo[o] = __float2bfloat16(x - __bfloat162float(h));
}

// warp-per-node SpMM: gathers use L2-evict-last cache hint to keep z resident
__global__ void k_spmm(const float* __restrict__ zin, float* __restrict__ zout) {
    int w = (blockIdx.x * blockDim.x + threadIdx.x) >> 5;
    int lane = threadIdx.x & 31;
    if (w >= NN) return;
    unsigned long long pol = mk_evict_last_policy();
    int s = g_off[w], e = g_off[w + 1];
    float dn = g_dinv[w];
    float ws = dn * dn;
    float4 acc = ld_el4(zin + (size_t)w * HF + lane * 4, pol);
    acc.x *= ws; acc.y *= ws; acc.z *= ws; acc.w *= ws;
#pragma unroll 4
    for (int j = s; j < e; ++j) {
        int2 e2 = g_epk[j];
        float wt = __int_as_float(e2.y);
        float4 v = ld_el4(zin + (size_t)e2.x * HF + lane * 4, pol);
        acc.x += wt * v.x; acc.y += wt * v.y; acc.z += wt * v.z; acc.w += wt * v.w;
    }
    ((float4*)(zout + (size_t)w * HF))[lane] = acc;
}

// ---------------- HMMA bf16 3-term GEMM ----------------
// MODE 0: bias+LN+ReLU epilogue -> C
// MODE 1: raw fp32 accumulator -> C (ld=HF), no bias/LN
// MODE 2: add addend[row][c] (streamed), then bias+LN+ReLU -> C
// ACS: A loads streamed (ld.cs)   CCS: C stores streamed (st.cs)
#define OFF_PAR 0
#define TILE_B  (128 * ASTR * 2)      // 18432
#define OFF_AH  2048
#define OFF_AL  (OFF_AH + TILE_B)
#define OFF_BH  (OFF_AH + 2 * TILE_B)
#define OFF_BL  (OFF_AH + 3 * TILE_B)
#define SMEM_DYN (OFF_AH + 4 * TILE_B)   // 75776

template <int K, int MODE, int ACS, int CCS>
__global__ __launch_bounds__(256, 2)
void k_mma(const float* __restrict__ A, int lda, const float* __restrict__ rowscale,
           const bf16* __restrict__ Whi, const bf16* __restrict__ Wlo, int ldb,
           const float* __restrict__ bias, const float* __restrict__ gamma,
           const float* __restrict__ beta,
           const float* __restrict__ addend,
           float* __restrict__ C, int ldc, int noff)
{
    extern __shared__ char smem[];
    bf16* sAh = (bf16*)(smem + OFF_AH);
    bf16* sAl = (bf16*)(smem + OFF_AL);
    bf16* sBh = (bf16*)(smem + OFF_BH);
    bf16* sBl = (bf16*)(smem + OFF_BL);
    uint32_t sbase = smem_to_u32(smem);

    const int t = threadIdx.x, lane = t & 31, wid = t >> 5;
    const int warp_m = wid & 1, warp_n = wid >> 1;   // 2 (M) x 4 (N)
    const int m0 = blockIdx.x * 128;

    if (MODE != 1 && t < 128) {
        ((float*)(smem + OFF_PAR))[t]       = bias[t];
        ((float*)(smem + OFF_PAR))[128 + t] = gamma[t];
        ((float*)(smem + OFF_PAR))[256 + t] = beta[t];
    }

    float acc[4][4][4];
#pragma unroll
    for (int i = 0; i < 4; ++i)
#pragma unroll
        for (int j = 0; j < 4; ++j)
#pragma unroll
            for (int u = 0; u < 4; ++u) acc[i][j][u] = 0.f;

    const int a_row = warp_m * 64 + (lane & 7) + ((lane >> 3) & 1) * 8;
    const int a_col = (lane >> 4) * 8;
    const int b_row = warp_n * 32 + (lane & 7);
    const int b_col = ((lane >> 3) & 1) * 8;

    for (int k0 = 0; k0 < K; k0 += BK) {
        for (int i = t; i < 2048; i += 256) {
            int row = i >> 4, cq = (i & 15) * 4;
            float4 v = make_float4(0.f, 0.f, 0.f, 0.f);
            int gm = m0 + row;
            if (gm < NN) {
                const float* ap = A + (size_t)gm * lda + k0 + cq;
                v = ACS ? ld_cs4(ap) : *(const float4*)ap;
                if (rowscale) {
                    float sc = rowscale[gm];
                    v.x *= sc; v.y *= sc; v.z *= sc; v.w *= sc;
                }
            }
            uint2 H, L;
            split2(v.x, v.y, H.x, L.x);
            split2(v.z, v.w, H.y, L.y);
            *(uint2*)(sAh + row * ASTR + cq) = H;
            *(uint2*)(sAl + row * ASTR + cq) = L;
            *(uint2*)(sBh + row * ASTR + cq) = *(const uint2*)(Whi + (size_t)row * ldb + k0 + cq);
            *(uint2*)(sBl + row * ASTR + cq) = *(const uint2*)(Wlo + (size_t)row * ldb + k0 + cq);
        }
        __syncthreads();

#pragma unroll
        for (int kk = 0; kk < BK; kk += 16) {
            uint32_t bh[4][2], bl[4][2];
#pragma unroll
            for (int nt = 0; nt < 4; ++nt) {
                uint32_t boff = (uint32_t)(((b_row + nt * 8) * ASTR + kk + b_col) * 2);
                ldsm2(bh[nt], sbase + OFF_BH + boff);
                ldsm2(bl[nt], sbase + OFF_BL + boff);
            }
#pragma unroll
            for (int mt = 0; mt < 4; ++mt) {
                uint32_t ah[4], al[4];
                uint32_t aoff = (uint32_t)(((a_row + mt * 16) * ASTR + kk + a_col) * 2);
                ldsm4(ah, sbase + OFF_AH + aoff);
                ldsm4(al, sbase + OFF_AL + aoff);
#pragma unroll
                for (int nt = 0; nt < 4; ++nt) {
                    mma16816(acc[mt][nt], ah, bh[nt]);
                    mma16816(acc[mt][nt], ah, bl[nt]);
                    mma16816(acc[mt][nt], al, bh[nt]);
                }
            }
        }
        __syncthreads();
    }

    if (MODE == 1) {
#pragma unroll
        for (int mt = 0; mt < 4; ++mt) {
#pragma unroll
            for (int rh = 0; rh < 2; ++rh) {
                int r = warp_m * 64 + mt * 16 + (lane >> 2) + rh * 8;
                int gm = m0 + r;
                if (gm >= NN) continue;
                float* cp = C + (size_t)gm * HF;
#pragma unroll
                for (int nt = 0; nt < 4; ++nt) {
                    int c = warp_n * 32 + nt * 8 + (lane & 3) * 2;
                    float2 v = make_float2(acc[mt][nt][2 * rh], acc[mt][nt][2 * rh + 1]);
                    if (CCS) st_cs2(cp + c, v);
                    else *(float2*)(cp + c) = v;
                }
            }
        }
        return;
    }

    // ---- epilogue in registers (MODE 0 / 2) ----
    const float* pb = (const float*)(smem + OFF_PAR);
    const float* pg = pb + 128;
    const float* pe = pb + 256;
    float* s_sum = (float*)(smem + OFF_AH);
    float* s_sq  = s_sum + 512;
    float* s_mu  = s_sq + 512;
    float* s_inv = s_mu + 128;

#pragma unroll
    for (int mt = 0; mt < 4; ++mt) {
#pragma unroll
        for (int rh = 0; rh < 2; ++rh) {
            int r = warp_m * 64 + mt * 16 + (lane >> 2) + rh * 8;
            int gm = m0 + r;
            const float* ap = (MODE == 2 && gm < NN) ? (addend + (size_t)gm * HF) : nullptr;
            float s = 0.f, q = 0.f;
#pragma unroll
            for (int nt = 0; nt < 4; ++nt) {
                int c = warp_n * 32 + nt * 8 + (lane & 3) * 2;
                float x0 = acc[mt][nt][2 * rh]     + pb[c];
                float x1 = acc[mt][nt][2 * rh + 1] + pb[c + 1];
                if (MODE == 2 && ap) {
                    float2 ad = ld_cs2(ap + c);
                    x0 += ad.x; x1 += ad.y;
                }
                acc[mt][nt][2 * rh]     = x0;
                acc[mt][nt][2 * rh + 1] = x1;
                s += x0 + x1;
                q += x0 * x0 + x1 * x1;
            }
            s += __shfl_xor_sync(0xffffffffu, s, 1);
            q += __shfl_xor_sync(0xffffffffu, q, 1);
            s += __shfl_xor_sync(0xffffffffu, s, 2);
            q += __shfl_xor_sync(0xffffffffu, q, 2);
            if ((lane & 3) == 0) {
                s_sum[warp_n * 128 + r] = s;
                s_sq [warp_n * 128 + r] = q;
            }
        }
    }
    __syncthreads();
    if (t < 128) {
        float s = s_sum[t] + s_sum[128 + t] + s_sum[256 + t] + s_sum[384 + t];
        float q = s_sq [t] + s_sq [128 + t] + s_sq [256 + t] + s_sq [384 + t];
        float mu  = s * (1.0f / 128.0f);
        float var = q * (1.0f / 128.0f) - mu * mu;
        s_mu[t]  = mu;
        s_inv[t] = rsqrtf(var + 1e-5f);
    }
    __syncthreads();
#pragma unroll
    for (int mt = 0; mt < 4; ++mt) {
#pragma unroll
        for (int rh = 0; rh < 2; ++rh) {
            int r = warp_m * 64 + mt * 16 + (lane >> 2) + rh * 8;
            int gm = m0 + r;
            if (gm >= NN) continue;
            float mu = s_mu[r], inv = s_inv[r];
            float* cp = C + (size_t)gm * ldc + noff;
#pragma unroll
            for (int nt = 0; nt < 4; ++nt) {
                int c = warp_n * 32 + nt * 8 + (lane & 3) * 2;
                float2 y;
                y.x = fmaxf((acc[mt][nt][2 * rh]     - mu) * inv * pg[c]     + pe[c],     0.f);
                y.y = fmaxf((acc[mt][nt][2 * rh + 1] - mu) * inv * pg[c + 1] + pe[c + 1], 0.f);
                if (CCS) st_cs2(cp + c, y);
                else *(float2*)(cp + c) = y;
            }
        }
    }
}

// ---------------- launch ----------------
extern "C" void kernel_launch(void* const* d_in, const int* in_sizes, int n_in,
                              void* d_out, int out_size)
{
    const void*  ei     = d_in[0];
    const float* feats  = (const float*)d_in[1];
    const float* W_uni  = (const float*)d_in[2];
    const float* b_uni  = (const float*)d_in[3];
    const float* g_uni  = (const float*)d_in[4];
    const float* be_uni = (const float*)d_in[5];
    const float* W_ind  = (const float*)d_in[6];
    const float* b_ind  = (const float*)d_in[7];
    const float* g_ind  = (const float*)d_in[8];
    const float* be_ind = (const float*)d_in[9];
    const float* W_rel  = (const float*)d_in[10];
    const float* b_rel  = (const float*)d_in[11];
    const float* g_rel  = (const float*)d_in[12];
    const float* be_rel = (const float*)d_in[13];
    float* out = (float*)d_out;

    // one-time resource creation (first call = correctness run, pre-baseline).
    static cudaStream_t s2 = nullptr, s3 = nullptr;
    static cudaEvent_t evStart, evW, evH, evZa, evZb, evZc, evNs1, evR1, evDone;
    if (!s2) {
        cudaStreamCreateWithFlags(&s2, cudaStreamNonBlocking);
        cudaStreamCreateWithFlags(&s3, cudaStreamNonBlocking);
        cudaEvent_t* evs[] = { &evStart, &evW, &evH, &evZa, &evZb, &evZc,
                               &evNs1, &evR1, &evDone };
        for (auto e : evs) cudaEventCreateWithFlags(e, cudaEventDisableTiming);
        cudaFuncSetAttribute(k_mma<KIN, 0, 1, 0>, cudaFuncAttributeMaxDynamicSharedMemorySize, SMEM_DYN);
        cudaFuncSetAttribute(k_mma<HF, 0, 0, 1>,  cudaFuncAttributeMaxDynamicSharedMemorySize, SMEM_DYN);
        cudaFuncSetAttribute(k_mma<256, 1, 1, 1>, cudaFuncAttributeMaxDynamicSharedMemorySize, SMEM_DYN);
        cudaFuncSetAttribute(k_mma<256, 2, 1, 0>, cudaFuncAttributeMaxDynamicSharedMemorySize, SMEM_DYN);
    }

    float *ph, *pza, *pzb, *pzc, *pcat, *pinv, *pracc;
    bf16 *pwuh, *pwul, *pwih, *pwil, *pwrh, *pwrl;
    cudaGetSymbolAddress((void**)&ph,    g_h);
    cudaGetSymbolAddress((void**)&pza,   g_za);
    cudaGetSymbolAddress((void**)&pzb,   g_zb);
    cudaGetSymbolAddress((void**)&pzc,   g_zc);
    cudaGetSymbolAddress((void**)&pcat,  g_cat);
    cudaGetSymbolAddress((void**)&pinv,  g_invnorm);
    cudaGetSymbolAddress((void**)&pracc, g_racc);
    cudaGetSymbolAddress((void**)&pwuh,  g_wu_hi);
    cudaGetSymbolAddress((void**)&pwul,  g_wu_lo);
    cudaGetSymbolAddress((void**)&pwih,  g_wi_hi);
    cudaGetSymbolAddress((void**)&pwil,  g_wi_lo);
    cudaGetSymbolAddress((void**)&pwrh,  g_wr_hi);
    cudaGetSymbolAddress((void**)&pwrl,  g_wr_lo);

    // fork s2/s3 off the (captured) default stream
    cudaEventRecord(evStart, 0);
    cudaStreamWaitEvent(s2, evStart, 0);
    cudaStreamWaitEvent(s3, evStart, 0);

    // ---- main stream: CSR build chain ----
    k_detect<<<1, 32>>>(ei);
    k_init_cnt<<<(NN + 255) / 256, 256>>>();
    k_count<<<(EE + 255) / 256, 256>>>(ei);
    k_scan1<<<NBLK, 1024>>>();
    k_scan2<<<1, 128>>>();
    k_scan3<<<NBLK, 1024>>>();
    k_scatter<<<(EE + 255) / 256, 256>>>();

    // ---- s3: weight prep (concurrent with invnorm on s2) ----
    k_wprep<<<(HF * KIN + 255) / 256, 256, 0, s3>>>(W_uni, pwuh, pwul, KIN, HF * KIN);
    k_wprep<<<(4 * HF * HF + 255) / 256, 256, 0, s3>>>(W_ind, pwih, pwil, HF, 4 * HF * HF);
    k_wprep<<<(HF * KIN + 255) / 256, 256, 0, s3>>>(W_rel, pwrh, pwrl, KIN, HF * KIN);
    cudaEventRecord(evW, s3);

    // ---- s2: invnorm -> uni GEMM (rowscale fused, feats streamed) -> hop0 ----
    k_invnorm<<<NN / 8, 256, 0, s2>>>(feats);
    cudaStreamWaitEvent(s2, evW, 0);
    k_mma<KIN, 0, 1, 0><<<GRID_M, 256, SMEM_DYN, s2>>>(
        feats, KIN, pinv, pwuh, pwul, KIN,
        b_uni, g_uni, be_uni, nullptr, ph, HF, 0);
    cudaEventRecord(evH, s2);
    k_mma<HF, 0, 0, 1><<<GRID_M, 256, SMEM_DYN, s2>>>(
        ph, HF, nullptr, pwih, pwil, HF,
        b_ind, g_ind, be_ind, nullptr, pcat, 4 * HF, 0);

    // ---- main: SpMM chain (gathers evict-last), overlapped with hop GEMMs ----
    cudaStreamWaitEvent(0, evH, 0);
    k_spmm<<<NN / 8, 256>>>(ph, pza);
    cudaEventRecord(evZa, 0);
    k_spmm<<<NN / 8, 256>>>(pza, pzb);
    cudaEventRecord(evZb, 0);
    k_spmm<<<NN / 8, 256>>>(pzb, pzc);
    cudaEventRecord(evZc, 0);

    // ---- s2: hop GEMMs as their inputs land (cat stores streamed) ----
    cudaStreamWaitEvent(s2, evZa, 0);
    k_mma<HF, 0, 0, 1><<<GRID_M, 256, SMEM_DYN, s2>>>(
        pza, HF, nullptr, pwih + 1 * HF * HF, pwil + 1 * HF * HF, HF,
        b_ind + 1 * HF, g_ind + 1 * HF, be_ind + 1 * HF, nullptr,
        pcat, 4 * HF, 1 * HF);
    cudaEventRecord(evNs1, s2);
    cudaStreamWaitEvent(s2, evZb, 0);
    k_mma<HF, 0, 0, 1><<<GRID_M, 256, SMEM_DYN, s2>>>(
        pzb, HF, nullptr, pwih + 2 * HF * HF, pwil + 2 * HF * HF, HF,
        b_ind + 2 * HF, g_ind + 2 * HF, be_ind + 2 * HF, nullptr,
        pcat, 4 * HF, 2 * HF);
    cudaStreamWaitEvent(s2, evZc, 0);
    k_mma<HF, 0, 0, 1><<<GRID_M, 256, SMEM_DYN, s2>>>(
        pzc, HF, nullptr, pwih + 3 * HF * HF, pwil + 3 * HF * HF, HF,
        b_ind + 3 * HF, g_ind + 3 * HF, be_ind + 3 * HF, nullptr,
        pcat, 4 * HF, 3 * HF);

    // ---- s3: rel half 1 (hops 0-1, cat streamed in, racc streamed out) ----
    cudaStreamWaitEvent(s3, evNs1, 0);
    k_mma<256, 1, 1, 1><<<GRID_M, 256, SMEM_DYN, s3>>>(
        pcat, 4 * HF, nullptr, pwrh, pwrl, KIN,
        nullptr, nullptr, nullptr, nullptr, pracc, HF, 0);
    cudaEventRecord(evR1, s3);

    // ---- s2 tail: rel half 2 (hops 2-3) + racc + bias + LN + ReLU -> out ----
    cudaStreamWaitEvent(s2, evR1, 0);
    k_mma<256, 2, 1, 0><<<GRID_M, 256, SMEM_DYN, s2>>>(
        pcat + 256, 4 * HF, nullptr, pwrh + 256, pwrl + 256, KIN,
        b_rel, g_rel, be_rel, pracc, out, HF, 0);
    cudaEventRecord(evDone, s2);

    // join
    cudaStreamWaitEvent(0, evDone, 0);
}

// round 17
// speedup vs baseline: 1.1989x; 1.1989x over previous
#include <cuda_runtime.h>
#include <cuda_bf16.h>
#include <cstdint>
#include <cstddef>

#define NN 100000
#define EE 1600000
#define HF 128
#define KIN 512
#define NBLK 98     // ceil(NN/1024)
#define GRID_M 782  // ceil(NN/128)
#define BK 64
#define ASTR 72     // padded smem row stride (bf16 elems)

typedef __nv_bfloat16 bf16;

// ---------------- scratch (static device globals; no allocations) ----------------
__device__ int   g_is64;
__device__ float g_invnorm[NN];
__device__ int   g_cnt[NN];
__device__ float g_dinv[NN];
__device__ int   g_erow[EE];
__device__ int   g_ecol0[EE];
__device__ int   g_off[NN + 1];
__device__ int   g_cursor[NN];
__device__ int   g_bsum[128];
__device__ int   g_boff[128];
__device__ int2  g_epk[EE];          // packed (col, w-bits)

__device__ float g_h  [(size_t)NN * HF];
__device__ float g_za [(size_t)NN * HF];
__device__ float g_zb [(size_t)NN * HF];
__device__ float g_zc [(size_t)NN * HF];
__device__ float g_cat[(size_t)NN * 4 * HF];
__device__ float g_racc[(size_t)NN * HF];

// transposed + hi/lo split weights: Wt[n][k] = W[k][n]
__device__ bf16 g_wu_hi[HF * KIN];
__device__ bf16 g_wu_lo[HF * KIN];
__device__ bf16 g_wi_hi[4 * HF * HF];
__device__ bf16 g_wi_lo[4 * HF * HF];
__device__ bf16 g_wr_hi[HF * KIN];
__device__ bf16 g_wr_lo[HF * KIN];

// ---------------- helpers ----------------
__device__ __forceinline__ uint32_t smem_to_u32(const void* p) {
    uint32_t a;
    asm("{ .reg .u64 t; cvta.to.shared.u64 t, %1; cvt.u32.u64 %0, t; }" : "=r"(a) : "l"(p));
    return a;
}
__device__ __forceinline__ uint32_t bpack(bf16 a, bf16 b) {
    __nv_bfloat162 t(a, b);
    return *reinterpret_cast<uint32_t*>(&t);
}
__device__ __forceinline__ void split2(float a, float b, uint32_t& hi, uint32_t& lo) {
    bf16 ha = __float2bfloat16(a), hb = __float2bfloat16(b);
    float ra = a - __bfloat162float(ha);
    float rb = b - __bfloat162float(hb);
    hi = bpack(ha, hb);
    lo = bpack(__float2bfloat16(ra), __float2bfloat16(rb));
}
__device__ __forceinline__ void ldsm4(uint32_t* r, uint32_t a) {
    asm volatile("ldmatrix.sync.aligned.m8n8.x4.shared.b16 {%0,%1,%2,%3}, [%4];"
        : "=r"(r[0]), "=r"(r[1]), "=r"(r[2]), "=r"(r[3]) : "r"(a));
}
__device__ __forceinline__ void ldsm2(uint32_t* r, uint32_t a) {
    asm volatile("ldmatrix.sync.aligned.m8n8.x2.shared.b16 {%0,%1}, [%2];"
        : "=r"(r[0]), "=r"(r[1]) : "r"(a));
}
__device__ __forceinline__ void mma16816(float* c, const uint32_t* a, const uint32_t* b) {
    asm volatile("mma.sync.aligned.m16n8k16.row.col.f32.bf16.bf16.f32 "
        "{%0,%1,%2,%3}, {%4,%5,%6,%7}, {%8,%9}, {%0,%1,%2,%3};"
        : "+f"(c[0]), "+f"(c[1]), "+f"(c[2]), "+f"(c[3])
        : "r"(a[0]), "r"(a[1]), "r"(a[2]), "r"(a[3]), "r"(b[0]), "r"(b[1]));
}

// ---------------- preprocessing ----------------
__global__ void k_detect(const void* ei) {
    const unsigned int* p = (const unsigned int*)ei;
    int ok64 = 1;
    for (int i = threadIdx.x; i < 64; i += 32)
        if (p[2 * i + 1] != 0u) ok64 = 0;
    ok64 = __all_sync(0xffffffffu, ok64);
    if (threadIdx.x == 0) g_is64 = ok64;
}

__global__ void k_init_cnt() {
    int i = blockIdx.x * blockDim.x + threadIdx.x;
    if (i < NN) g_cnt[i] = 0;
}

__global__ void k_invnorm(const float* __restrict__ feats) {
    int w = (blockIdx.x * blockDim.x + threadIdx.x) >> 5;
    int lane = threadIdx.x & 31;
    if (w >= NN) return;
    const float4* p = (const float4*)(feats + (size_t)w * KIN);
    float ss = 0.f;
#pragma unroll
    for (int i = 0; i < 4; ++i) {
        float4 v = p[i * 32 + lane];
        ss += v.x * v.x + v.y * v.y + v.z * v.z + v.w * v.w;
    }
#pragma unroll
    for (int o = 16; o > 0; o >>= 1) ss += __shfl_xor_sync(0xffffffffu, ss, o);
    if (lane == 0) g_invnorm[w] = 1.0f / fmaxf(sqrtf(ss), 1e-12f);
}

__global__ void k_count(const void* ei) {
    int e = blockIdx.x * blockDim.x + threadIdx.x;
    if (e >= EE) return;
    int r, c;
    if (g_is64) {
        const long long* p = (const long long*)ei;
        r = (int)p[e]; c = (int)p[EE + e];
    } else {
        const int* p = (const int*)ei;
        r = p[e]; c = p[EE + e];
    }
    g_erow[e] = r;
    g_ecol0[e] = c;
    atomicAdd(&g_cnt[r], 1);
}

__global__ void k_scan1() {
    __shared__ int sm[1024];
    int t = threadIdx.x;
    int i = blockIdx.x * 1024 + t;
    int v = (i < NN) ? g_cnt[i] : 0;
    sm[t] = v;
    __syncthreads();
    for (int d = 1; d < 1024; d <<= 1) {
        int add = (t >= d) ? sm[t - d] : 0;
        __syncthreads();
        sm[t] += add;
        __syncthreads();
    }
    int incl = sm[t];
    if (i < NN) g_off[i] = incl - v;
    if (t == 1023) g_bsum[blockIdx.x] = incl;
}

__global__ void k_scan2() {
    __shared__ int sm[128];
    int t = threadIdx.x;
    int v = (t < NBLK) ? g_bsum[t] : 0;
    sm[t] = v;
    __syncthreads();
    for (int d = 1; d < 128; d <<= 1) {
        int add = (t >= d) ? sm[t - d] : 0;
        __syncthreads();
        sm[t] += add;
        __syncthreads();
    }
    g_boff[t] = sm[t] - v;
}

__global__ void k_scan3() {
    int t = threadIdx.x;
    int i = blockIdx.x * 1024 + t;
    if (i < NN) {
        int off = g_off[i] + g_boff[blockIdx.x];
        g_off[i] = off;
        g_cursor[i] = off;
        g_dinv[i] = rsqrtf((float)(g_cnt[i] + 1));
        if (i == 0) g_off[NN] = EE;
    }
}

__global__ void k_scatter() {
    int e = blockIdx.x * blockDim.x + threadIdx.x;
    if (e >= EE) return;
    int r = g_erow[e], c = g_ecol0[e];
    int pos = atomicAdd(&g_cursor[r], 1);
    g_epk[pos] = make_int2(c, __float_as_int(g_dinv[r] * g_dinv[c]));
}

// weight transpose + split: out[m][n][k] = W[m][k][n]
__global__ void k_wprep(const float* __restrict__ W, bf16* __restrict__ hi,
                        bf16* __restrict__ lo, int K, int total) {
    int o = blockIdx.x * blockDim.x + threadIdx.x;
    if (o >= total) return;
    int k = o % K;
    int rem = o / K;
    int n = rem % HF;
    int m = rem / HF;
    float x = W[(size_t)m * K * HF + (size_t)k * HF + n];
    bf16 h = __float2bfloat16(x);
    hi[o] = h;
    lo[o] = __float2bfloat16(x - __bfloat162float(h));
}

// warp-per-node SpMM with self-loop, CSR, register accumulation
__global__ void k_spmm(const float* __restrict__ zin, float* __restrict__ zout) {
    int w = (blockIdx.x * blockDim.x + threadIdx.x) >> 5;
    int lane = threadIdx.x & 31;
    if (w >= NN) return;
    int s = g_off[w], e = g_off[w + 1];
    float dn = g_dinv[w];
    float ws = dn * dn;
    float4 acc = ((const float4*)(zin + (size_t)w * HF))[lane];
    acc.x *= ws; acc.y *= ws; acc.z *= ws; acc.w *= ws;
#pragma unroll 4
    for (int j = s; j < e; ++j) {
        int2 e2 = g_epk[j];
        float wt = __int_as_float(e2.y);
        float4 v = ((const float4*)(zin + (size_t)e2.x * HF))[lane];
        acc.x += wt * v.x; acc.y += wt * v.y; acc.z += wt * v.z; acc.w += wt * v.w;
    }
    ((float4*)(zout + (size_t)w * HF))[lane] = acc;
}

// ---------------- HMMA bf16 3-term GEMM ----------------
// MODE 0: bias+LN+ReLU epilogue -> C
// MODE 1: raw fp32 accumulator -> C (ld=HF), no bias/LN
// MODE 2: add addend[row][c], then bias+LN+ReLU -> C
#define OFF_PAR 0
#define TILE_B  (128 * ASTR * 2)      // 18432
#define OFF_AH  2048
#define OFF_AL  (OFF_AH + TILE_B)
#define OFF_BH  (OFF_AH + 2 * TILE_B)
#define OFF_BL  (OFF_AH + 3 * TILE_B)
#define SMEM_DYN (OFF_AH + 4 * TILE_B)   // 75776

template <int K, int MODE>
__global__ __launch_bounds__(256, 2)
void k_mma(const float* __restrict__ A, int lda, const float* __restrict__ rowscale,
           const bf16* __restrict__ Whi, const bf16* __restrict__ Wlo, int ldb,
           const float* __restrict__ bias, const float* __restrict__ gamma,
           const float* __restrict__ beta,
           const float* __restrict__ addend,
           float* __restrict__ C, int ldc, int noff)
{
    extern __shared__ char smem[];
    bf16* sAh = (bf16*)(smem + OFF_AH);
    bf16* sAl = (bf16*)(smem + OFF_AL);
    bf16* sBh = (bf16*)(smem + OFF_BH);
    bf16* sBl = (bf16*)(smem + OFF_BL);
    uint32_t sbase = smem_to_u32(smem);

    const int t = threadIdx.x, lane = t & 31, wid = t >> 5;
    const int warp_m = wid & 1, warp_n = wid >> 1;   // 2 (M) x 4 (N)
    const int m0 = blockIdx.x * 128;

    if (MODE != 1 && t < 128) {
        ((float*)(smem + OFF_PAR))[t]       = bias[t];
        ((float*)(smem + OFF_PAR))[128 + t] = gamma[t];
        ((float*)(smem + OFF_PAR))[256 + t] = beta[t];
    }

    float acc[4][4][4];
#pragma unroll
    for (int i = 0; i < 4; ++i)
#pragma unroll
        for (int j = 0; j < 4; ++j)
#pragma unroll
            for (int u = 0; u < 4; ++u) acc[i][j][u] = 0.f;

    const int a_row = warp_m * 64 + (lane & 7) + ((lane >> 3) & 1) * 8;
    const int a_col = (lane >> 4) * 8;
    const int b_row = warp_n * 32 + (lane & 7);
    const int b_col = ((lane >> 3) & 1) * 8;

    for (int k0 = 0; k0 < K; k0 += BK) {
        for (int i = t; i < 2048; i += 256) {
            int row = i >> 4, cq = (i & 15) * 4;
            float4 v = make_float4(0.f, 0.f, 0.f, 0.f);
            int gm = m0 + row;
            if (gm < NN) {
                v = *(const float4*)(A + (size_t)gm * lda + k0 + cq);
                if (rowscale) {
                    float sc = rowscale[gm];
                    v.x *= sc; v.y *= sc; v.z *= sc; v.w *= sc;
                }
            }
            uint2 H, L;
            split2(v.x, v.y, H.x, L.x);
            split2(v.z, v.w, H.y, L.y);
            *(uint2*)(sAh + row * ASTR + cq) = H;
            *(uint2*)(sAl + row * ASTR + cq) = L;
            *(uint2*)(sBh + row * ASTR + cq) = *(const uint2*)(Whi + (size_t)row * ldb + k0 + cq);
            *(uint2*)(sBl + row * ASTR + cq) = *(const uint2*)(Wlo + (size_t)row * ldb + k0 + cq);
        }
        __syncthreads();

#pragma unroll
        for (int kk = 0; kk < BK; kk += 16) {
            uint32_t bh[4][2], bl[4][2];
#pragma unroll
            for (int nt = 0; nt < 4; ++nt) {
                uint32_t boff = (uint32_t)(((b_row + nt * 8) * ASTR + kk + b_col) * 2);
                ldsm2(bh[nt], sbase + OFF_BH + boff);
                ldsm2(bl[nt], sbase + OFF_BL + boff);
            }
#pragma unroll
            for (int mt = 0; mt < 4; ++mt) {
                uint32_t ah[4], al[4];
                uint32_t aoff = (uint32_t)(((a_row + mt * 16) * ASTR + kk + a_col) * 2);
                ldsm4(ah, sbase + OFF_AH + aoff);
                ldsm4(al, sbase + OFF_AL + aoff);
#pragma unroll
                for (int nt = 0; nt < 4; ++nt) {
                    mma16816(acc[mt][nt], ah, bh[nt]);
                    mma16816(acc[mt][nt], ah, bl[nt]);
                    mma16816(acc[mt][nt], al, bh[nt]);
                }
            }
        }
        __syncthreads();
    }

    if (MODE == 1) {
#pragma unroll
        for (int mt = 0; mt < 4; ++mt) {
#pragma unroll
            for (int rh = 0; rh < 2; ++rh) {
                int r = warp_m * 64 + mt * 16 + (lane >> 2) + rh * 8;
                int gm = m0 + r;
                if (gm >= NN) continue;
                float* cp = C + (size_t)gm * HF;
#pragma unroll
                for (int nt = 0; nt < 4; ++nt) {
                    int c = warp_n * 32 + nt * 8 + (lane & 3) * 2;
                    *(float2*)(cp + c) = make_float2(acc[mt][nt][2 * rh], acc[mt][nt][2 * rh + 1]);
                }
            }
        }
        return;
    }

    // ---- epilogue in registers (MODE 0 / 2) ----
    const float* pb = (const float*)(smem + OFF_PAR);
    const float* pg = pb + 128;
    const float* pe = pb + 256;
    float* s_sum = (float*)(smem + OFF_AH);
    float* s_sq  = s_sum + 512;
    float* s_mu  = s_sq + 512;
    float* s_inv = s_mu + 128;

#pragma unroll
    for (int mt = 0; mt < 4; ++mt) {
#pragma unroll
        for (int rh = 0; rh < 2; ++rh) {
            int r = warp_m * 64 + mt * 16 + (lane >> 2) + rh * 8;
            int gm = m0 + r;
            const float* ap = (MODE == 2 && gm < NN) ? (addend + (size_t)gm * HF) : nullptr;
            float s = 0.f, q = 0.f;
#pragma unroll
            for (int nt = 0; nt < 4; ++nt) {
                int c = warp_n * 32 + nt * 8 + (lane & 3) * 2;
                float x0 = acc[mt][nt][2 * rh]     + pb[c];
                float x1 = acc[mt][nt][2 * rh + 1] + pb[c + 1];
                if (MODE == 2 && ap) {
                    float2 ad = *(const float2*)(ap + c);
                    x0 += ad.x; x1 += ad.y;
                }
                acc[mt][nt][2 * rh]     = x0;
                acc[mt][nt][2 * rh + 1] = x1;
                s += x0 + x1;
                q += x0 * x0 + x1 * x1;
            }
            s += __shfl_xor_sync(0xffffffffu, s, 1);
            q += __shfl_xor_sync(0xffffffffu, q, 1);
            s += __shfl_xor_sync(0xffffffffu, s, 2);
            q += __shfl_xor_sync(0xffffffffu, q, 2);
            if ((lane & 3) == 0) {
                s_sum[warp_n * 128 + r] = s;
                s_sq [warp_n * 128 + r] = q;
            }
        }
    }
    __syncthreads();
    if (t < 128) {
        float s = s_sum[t] + s_sum[128 + t] + s_sum[256 + t] + s_sum[384 + t];
        float q = s_sq [t] + s_sq [128 + t] + s_sq [256 + t] + s_sq [384 + t];
        float mu  = s * (1.0f / 128.0f);
        float var = q * (1.0f / 128.0f) - mu * mu;
        s_mu[t]  = mu;
        s_inv[t] = rsqrtf(var + 1e-5f);
    }
    __syncthreads();
#pragma unroll
    for (int mt = 0; mt < 4; ++mt) {
#pragma unroll
        for (int rh = 0; rh < 2; ++rh) {
            int r = warp_m * 64 + mt * 16 + (lane >> 2) + rh * 8;
            int gm = m0 + r;
            if (gm >= NN) continue;
            float mu = s_mu[r], inv = s_inv[r];
            float* cp = C + (size_t)gm * ldc + noff;
#pragma unroll
            for (int nt = 0; nt < 4; ++nt) {
                int c = warp_n * 32 + nt * 8 + (lane & 3) * 2;
                float2 y;
                y.x = fmaxf((acc[mt][nt][2 * rh]     - mu) * inv * pg[c]     + pe[c],     0.f);
                y.y = fmaxf((acc[mt][nt][2 * rh + 1] - mu) * inv * pg[c + 1] + pe[c + 1], 0.f);
                *(float2*)(cp + c) = y;
            }
        }
    }
}

// ---------------- launch ----------------
extern "C" void kernel_launch(void* const* d_in, const int* in_sizes, int n_in,
                              void* d_out, int out_size)
{
    const void*  ei     = d_in[0];
    const float* feats  = (const float*)d_in[1];
    const float* W_uni  = (const float*)d_in[2];
    const float* b_uni  = (const float*)d_in[3];
    const float* g_uni  = (const float*)d_in[4];
    const float* be_uni = (const float*)d_in[5];
    const float* W_ind  = (const float*)d_in[6];
    const float* b_ind  = (const float*)d_in[7];
    const float* g_ind  = (const float*)d_in[8];
    const float* be_ind = (const float*)d_in[9];
    const float* W_rel  = (const float*)d_in[10];
    const float* b_rel  = (const float*)d_in[11];
    const float* g_rel  = (const float*)d_in[12];
    const float* be_rel = (const float*)d_in[13];
    float* out = (float*)d_out;

    // one-time resource creation (first call = correctness run, pre-baseline).
    static cudaStream_t s2 = nullptr, s3 = nullptr;
    static cudaEvent_t evStart, evW, evH, evZa, evZb, evZc, evNs1, evR1, evDone;
    if (!s2) {
        cudaStreamCreateWithFlags(&s2, cudaStreamNonBlocking);
        cudaStreamCreateWithFlags(&s3, cudaStreamNonBlocking);
        cudaEventCreateWithFlags(&evStart, cudaEventDisableTiming);
        cudaEventCreateWithFlags(&evW,     cudaEventDisableTiming);
        cudaEventCreateWithFlags(&evH,     cudaEventDisableTiming);
        cudaEventCreateWithFlags(&evZa,    cudaEventDisableTiming);
        cudaEventCreateWithFlags(&evZb,    cudaEventDisableTiming);
        cudaEventCreateWithFlags(&evZc,    cudaEventDisableTiming);
        cudaEventCreateWithFlags(&evNs1,   cudaEventDisableTiming);
        cudaEventCreateWithFlags(&evR1,    cudaEventDisableTiming);
        cudaEventCreateWithFlags(&evDone,  cudaEventDisableTiming);
        cudaFuncSetAttribute(k_mma<KIN, 0>, cudaFuncAttributeMaxDynamicSharedMemorySize, SMEM_DYN);
        cudaFuncSetAttribute(k_mma<HF, 0>,  cudaFuncAttributeMaxDynamicSharedMemorySize, SMEM_DYN);
        cudaFuncSetAttribute(k_mma<256, 1>, cudaFuncAttributeMaxDynamicSharedMemorySize, SMEM_DYN);
        cudaFuncSetAttribute(k_mma<256, 2>, cudaFuncAttributeMaxDynamicSharedMemorySize, SMEM_DYN);
    }

    float *ph, *pza, *pzb, *pzc, *pcat, *pinv, *pracc;
    bf16 *pwuh, *pwul, *pwih, *pwil, *pwrh, *pwrl;
    cudaGetSymbolAddress((void**)&ph,    g_h);
    cudaGetSymbolAddress((void**)&pza,   g_za);
    cudaGetSymbolAddress((void**)&pzb,   g_zb);
    cudaGetSymbolAddress((void**)&pzc,   g_zc);
    cudaGetSymbolAddress((void**)&pcat,  g_cat);
    cudaGetSymbolAddress((void**)&pinv,  g_invnorm);
    cudaGetSymbolAddress((void**)&pracc, g_racc);
    cudaGetSymbolAddress((void**)&pwuh,  g_wu_hi);
    cudaGetSymbolAddress((void**)&pwul,  g_wu_lo);
    cudaGetSymbolAddress((void**)&pwih,  g_wi_hi);
    cudaGetSymbolAddress((void**)&pwil,  g_wi_lo);
    cudaGetSymbolAddress((void**)&pwrh,  g_wr_hi);
    cudaGetSymbolAddress((void**)&pwrl,  g_wr_lo);

    // fork s2/s3 off the (captured) default stream
    cudaEventRecord(evStart, 0);
    cudaStreamWaitEvent(s2, evStart, 0);
    cudaStreamWaitEvent(s3, evStart, 0);

    // ---- main stream: CSR build chain ----
    k_detect<<<1, 32>>>(ei);
    k_init_cnt<<<(NN + 255) / 256, 256>>>();
    k_count<<<(EE + 255) / 256, 256>>>(ei);
    k_scan1<<<NBLK, 1024>>>();
    k_scan2<<<1, 128>>>();
    k_scan3<<<NBLK, 1024>>>();
    k_scatter<<<(EE + 255) / 256, 256>>>();

    // ---- s3: weight prep (concurrent with invnorm on s2) ----
    k_wprep<<<(HF * KIN + 255) / 256, 256, 0, s3>>>(W_uni, pwuh, pwul, KIN, HF * KIN);
    k_wprep<<<(4 * HF * HF + 255) / 256, 256, 0, s3>>>(W_ind, pwih, pwil, HF, 4 * HF * HF);
    k_wprep<<<(HF * KIN + 255) / 256, 256, 0, s3>>>(W_rel, pwrh, pwrl, KIN, HF * KIN);
    cudaEventRecord(evW, s3);

    // ---- s2: invnorm -> uni GEMM (rowscale fused) -> hop0 ----
    k_invnorm<<<NN / 8, 256, 0, s2>>>(feats);
    cudaStreamWaitEvent(s2, evW, 0);
    k_mma<KIN, 0><<<GRID_M, 256, SMEM_DYN, s2>>>(feats, KIN, pinv, pwuh, pwul, KIN,
                                                 b_uni, g_uni, be_uni, nullptr, ph, HF, 0);
    cudaEventRecord(evH, s2);
    k_mma<HF, 0><<<GRID_M, 256, SMEM_DYN, s2>>>(ph, HF, nullptr, pwih, pwil, HF,
                                                b_ind, g_ind, be_ind, nullptr,
                                                pcat, 4 * HF, 0);

    // ---- main: SpMM chain, overlapped with hop GEMMs on s2 ----
    cudaStreamWaitEvent(0, evH, 0);
    k_spmm<<<NN / 8, 256>>>(ph, pza);
    cudaEventRecord(evZa, 0);
    k_spmm<<<NN / 8, 256>>>(pza, pzb);
    cudaEventRecord(evZb, 0);
    k_spmm<<<NN / 8, 256>>>(pzb, pzc);
    cudaEventRecord(evZc, 0);

    // ---- s2: hop GEMMs as their inputs land ----
    cudaStreamWaitEvent(s2, evZa, 0);
    k_mma<HF, 0><<<GRID_M, 256, SMEM_DYN, s2>>>(pza, HF, nullptr,
                                                pwih + 1 * HF * HF, pwil + 1 * HF * HF, HF,
                                                b_ind + 1 * HF, g_ind + 1 * HF, be_ind + 1 * HF,
                                                nullptr, pcat, 4 * HF, 1 * HF);
    cudaEventRecord(evNs1, s2);
    cudaStreamWaitEvent(s2, evZb, 0);
    k_mma<HF, 0><<<GRID_M, 256, SMEM_DYN, s2>>>(pzb, HF, nullptr,
                                                pwih + 2 * HF * HF, pwil + 2 * HF * HF, HF,
                                                b_ind + 2 * HF, g_ind + 2 * HF, be_ind + 2 * HF,
                                                nullptr, pcat, 4 * HF, 2 * HF);
    cudaStreamWaitEvent(s2, evZc, 0);
    k_mma<HF, 0><<<GRID_M, 256, SMEM_DYN, s2>>>(pzc, HF, nullptr,
                                                pwih + 3 * HF * HF, pwil + 3 * HF * HF, HF,
                                                b_ind + 3 * HF, g_ind + 3 * HF, be_ind + 3 * HF,
                                                nullptr, pcat, 4 * HF, 3 * HF);

    // ---- s3: rel half 1 (hops 0-1, cat cols 0..255) -> racc, overlapped w/ spmm2/3 ----
    cudaStreamWaitEvent(s3, evNs1, 0);
    k_mma<256, 1><<<GRID_M, 256, SMEM_DYN, s3>>>(pcat, 4 * HF, nullptr,
                                                 pwrh, pwrl, KIN,
                                                 nullptr, nullptr, nullptr, nullptr,
                                                 pracc, HF, 0);
    cudaEventRecord(evR1, s3);

    // ---- s2 tail: rel half 2 (hops 2-3) + racc + bias + LN + ReLU -> out ----
    cudaStreamWaitEvent(s2, evR1, 0);
    k_mma<256, 2><<<GRID_M, 256, SMEM_DYN, s2>>>(pcat + 256, 4 * HF, nullptr,
                                                 pwrh + 256, pwrl + 256, KIN,
                                                 b_rel, g_rel, be_rel, pracc,
                                                 out, HF, 0);
    cudaEventRecord(evDone, s2);

    // join
    cudaStreamWaitEvent(0, evDone, 0);
}